// round 7
// baseline (speedup 1.0000x reference)
#include <cuda_runtime.h>
#include <math.h>

#define BB 8
#define TT 2048
#define HH 1024
#define G3 3072
#define NCTA 128
#define NTHR 512
#define FPAD 32      // one flag per 128B line
#define SHSTR 1032   // padded h row stride (floats)

typedef unsigned long long u64;

// ---------------- persistent scratch (device globals; zero-initialized) -----
__device__ float g_xproj[(size_t)TT * BB * G3];   // [t][b][3H]
__device__ float g_h[2][BB * HH];                 // double-buffered hidden state
__device__ unsigned int g_flags[NCTA * FPAD];     // grid-barrier flags (monotonic)

__device__ __forceinline__ void st_release_gpu(unsigned int* p, unsigned int v) {
    asm volatile("st.release.gpu.u32 [%0], %1;" :: "l"(p), "r"(v) : "memory");
}
__device__ __forceinline__ unsigned int ld_acquire_gpu(const unsigned int* p) {
    unsigned int v;
    asm volatile("ld.acquire.gpu.u32 %0, [%1];" : "=r"(v) : "l"(p) : "memory");
    return v;
}
// packed fp32x2 FMA (Blackwell)
__device__ __forceinline__ u64 fma2(u64 a, u64 b, u64 c) {
    u64 d;
    asm("fma.rn.f32x2 %0, %1, %2, %3;" : "=l"(d) : "l"(a), "l"(b), "l"(c));
    return d;
}
__device__ __forceinline__ float fold2(u64 v) {
    return __uint_as_float((unsigned)v) + __uint_as_float((unsigned)(v >> 32));
}
__device__ __forceinline__ float sigmoidf_(float v) {
    return 1.0f / (1.0f + expf(-v));
}

// ---------------- kernel A: x_proj = x @ W_ih^T + b_ih ----------------------
// (unchanged from R5: conflict-free Bs map tx+16u; scatters to [t][b][3H])
#define BM 64
#define BN 128
#define BKK 16
#define APAD 18
#define BPAD 18

__global__ void __launch_bounds__(256, 2) xproj_gemm_kernel(
    const float* __restrict__ x,     // [b][t][h]
    const float* __restrict__ Wih,   // [3H, H]
    const float* __restrict__ bih)   // [3H]
{
    __shared__ float As[BM * APAD];
    __shared__ float Bs[BN * BPAD];

    const int tid = threadIdx.x;
    const int m0 = blockIdx.y * BM;
    const int n0 = blockIdx.x * BN;
    const int tx = tid & 15;
    const int ty = tid >> 4;

    const int ldRow = tid >> 2;
    const int ldCol = (tid & 3) * 4;

    const float* aPtr  = x   + (size_t)(m0 + ldRow) * HH + ldCol;
    const float* bPtr0 = Wih + (size_t)(n0 + ldRow) * HH + ldCol;
    const float* bPtr1 = Wih + (size_t)(n0 + ldRow + 64) * HH + ldCol;

    u64 acc[4][8];
#pragma unroll
    for (int i = 0; i < 4; ++i)
#pragma unroll
        for (int u = 0; u < 8; ++u) acc[i][u] = 0ull;

    for (int k0 = 0; k0 < HH; k0 += BKK) {
        float4 av  = *(const float4*)(aPtr  + k0);
        float4 bv0 = *(const float4*)(bPtr0 + k0);
        float4 bv1 = *(const float4*)(bPtr1 + k0);

        *(float2*)&As[ldRow * APAD + ldCol + 0] = make_float2(av.x, av.y);
        *(float2*)&As[ldRow * APAD + ldCol + 2] = make_float2(av.z, av.w);
        *(float2*)&Bs[ldRow * BPAD + ldCol + 0] = make_float2(bv0.x, bv0.y);
        *(float2*)&Bs[ldRow * BPAD + ldCol + 2] = make_float2(bv0.z, bv0.w);
        *(float2*)&Bs[(ldRow + 64) * BPAD + ldCol + 0] = make_float2(bv1.x, bv1.y);
        *(float2*)&Bs[(ldRow + 64) * BPAD + ldCol + 2] = make_float2(bv1.z, bv1.w);
        __syncthreads();

#pragma unroll
        for (int kk2 = 0; kk2 < BKK / 2; ++kk2) {
            u64 a2[4];
#pragma unroll
            for (int i = 0; i < 4; ++i)
                a2[i] = *(const u64*)&As[(ty * 4 + i) * APAD + kk2 * 2];
            u64 b2[8];
#pragma unroll
            for (int u = 0; u < 8; ++u)
                b2[u] = *(const u64*)&Bs[(tx + 16 * u) * BPAD + kk2 * 2];
#pragma unroll
            for (int i = 0; i < 4; ++i)
#pragma unroll
                for (int u = 0; u < 8; ++u)
                    acc[i][u] = fma2(a2[i], b2[u], acc[i][u]);
        }
        __syncthreads();
    }

#pragma unroll
    for (int i = 0; i < 4; ++i) {
        int m = m0 + ty * 4 + i;
        int b = m >> 11;
        int t = m & 2047;
        float* orow = g_xproj + ((size_t)t * BB + b) * G3 + n0;
#pragma unroll
        for (int u = 0; u < 8; ++u) {
            int c = tx + 16 * u;
            orow[c] = fold2(acc[i][u]) + __ldg(bih + n0 + c);
        }
    }
}

// ---------------- kernel B: persistent recurrence ---------------------------
// 512 threads = 16 warps. warp -> (p = wid&3, kq = wid>>2): col-pair {2p,2p+1},
// K-quarter kq. lane -> (b = lane&7, ks = lane>>3). W packed in smem as
// sWp[p][kp][row0..5] -> 6 W values per k-pair = 3 broadcast LDS.128.
// Partials combined across the 4 K-quarters via smem staging.
__global__ void __launch_bounds__(NTHR, 1) gru_recurrent_kernel(
    const float* __restrict__ Whh,   // [3H, H]
    const float* __restrict__ bhh,   // [3H]
    float* __restrict__ out)         // [B, T, H]
{
    extern __shared__ float smem[];
    u64*   sWp  = (u64*)smem;                    // [4][512][6] u64 = 96KB
    float* sh   = smem + (4 * 512 * 6) * 2;      // [8][SHSTR]  ~33KB
    float* sRed = sh + BB * SHSTR;               // [16 warps][8 b][8] = 4KB

    const int tid  = threadIdx.x;
    const int cta  = blockIdx.x;
    const int wid  = tid >> 5;
    const int lane = tid & 31;
    const int p    = wid & 3;
    const int kq   = wid >> 2;        // K-quarter 0..3
    const int b    = lane & 7;
    const int ks   = lane >> 3;

    // ---- pack W_hh: sWp[((pp*512 + kp)*6) + jloc*3 + g] = Whh k-pair ----
    for (int idx = tid; idx < 24 * 512; idx += NTHR) {
        int row = idx >> 9;          // 0..23
        int kp  = idx & 511;
        int jglob = row / 3;
        int g     = row % 3;
        int pp    = jglob >> 1;
        int jloc  = jglob & 1;
        const float* src = Whh + (size_t)(g * HH + cta * 8 + jglob) * HH + kp * 2;
        sWp[((pp * 512 + kp) * 6) + jloc * 3 + g] = *(const u64*)src;
    }
    __syncthreads();

    const int c0 = cta * 8 + 2 * p;
    float bh[6];
#pragma unroll
    for (int jl = 0; jl < 2; ++jl)
#pragma unroll
        for (int g = 0; g < 3; ++g)
            bh[jl * 3 + g] = bhh[g * HH + c0 + jl];

    const u64* wbase = sWp + (size_t)p * 512 * 6;
    const float* hrow = sh + b * SHSTR;

    const unsigned v0 = ld_acquire_gpu(&g_flags[cta * FPAD]);

    // step-0 xproj prefetch (warps kq==0, lanes<8)
    float xv[6];
    if (kq == 0 && lane < 8) {
        const float* px = g_xproj + (size_t)b * G3;   // t=0
#pragma unroll
        for (int g = 0; g < 3; ++g) {
            float2 v = *(const float2*)(px + g * HH + c0);
            xv[0 * 3 + g] = v.x;
            xv[1 * 3 + g] = v.y;
        }
    }

    for (int t = 0; t < TT; ++t) {
        // ---- stage h(t) into smem ----
        if (t == 0) {
            float4 z4 = make_float4(0.f, 0.f, 0.f, 0.f);
            for (int i = tid; i < (BB * SHSTR) / 4; i += NTHR)
                ((float4*)sh)[i] = z4;
        } else {
            const float* hin = g_h[t & 1];
#pragma unroll
            for (int i = 0; i < 4; ++i) {
                int lin = tid + i * NTHR;       // 0..2047 float4
                int bb  = lin >> 8;
                int k4  = lin & 255;
                ((float4*)(sh + bb * SHSTR))[k4] =
                    __ldcg(((const float4*)(hin + (size_t)bb * HH)) + k4);
            }
        }

        // prefetch next step's xproj during compute
        float xnx[6] = {0.f, 0.f, 0.f, 0.f, 0.f, 0.f};
        if (kq == 0 && lane < 8 && t + 1 < TT) {
            const float* px = g_xproj + ((size_t)(t + 1) * BB + b) * G3;
#pragma unroll
            for (int g = 0; g < 3; ++g) {
                float2 v = *(const float2*)(px + g * HH + c0);
                xnx[0 * 3 + g] = v.x;
                xnx[1 * 3 + g] = v.y;
            }
        }
        __syncthreads();

        // ---- partial dot products over this warp's K-quarter ----
        u64 acc0 = 0ull, acc1 = 0ull, acc2 = 0ull;
        u64 acc3 = 0ull, acc4 = 0ull, acc5 = 0ull;
        const int kp0 = kq * 128 + ks;
#pragma unroll 8
        for (int j = 0; j < 32; ++j) {
            int kp = kp0 + j * 4;
            const u64* wp = wbase + (size_t)kp * 6;
            ulonglong2 wA = *(const ulonglong2*)(wp + 0);
            ulonglong2 wB = *(const ulonglong2*)(wp + 2);
            ulonglong2 wC = *(const ulonglong2*)(wp + 4);
            u64 h2 = *(const u64*)(hrow + 2 * kp);
            acc0 = fma2(wA.x, h2, acc0);
            acc1 = fma2(wA.y, h2, acc1);
            acc2 = fma2(wB.x, h2, acc2);
            acc3 = fma2(wB.y, h2, acc3);
            acc4 = fma2(wC.x, h2, acc4);
            acc5 = fma2(wC.y, h2, acc5);
        }

        // fold + reduce over ks (lanes b, b+8, b+16, b+24)
        float s0 = fold2(acc0), s1 = fold2(acc1), s2 = fold2(acc2);
        float s3 = fold2(acc3), s4 = fold2(acc4), s5 = fold2(acc5);
#pragma unroll
        for (int off = 8; off <= 16; off <<= 1) {
            s0 += __shfl_xor_sync(0xffffffffu, s0, off);
            s1 += __shfl_xor_sync(0xffffffffu, s1, off);
            s2 += __shfl_xor_sync(0xffffffffu, s2, off);
            s3 += __shfl_xor_sync(0xffffffffu, s3, off);
            s4 += __shfl_xor_sync(0xffffffffu, s4, off);
            s5 += __shfl_xor_sync(0xffffffffu, s5, off);
        }

        // stage partials
        if (lane < 8) {
            float* dst = sRed + ((wid * 8 + b) * 8);
            dst[0] = s0; dst[1] = s1; dst[2] = s2;
            dst[3] = s3; dst[4] = s4; dst[5] = s5;
        }
        __syncthreads();

        // ---- combine 4 K-quarters + activations (warps kq==0, lanes<8) ----
        if (kq == 0 && lane < 8) {
            const float* r0 = sRed + (((0 * 4 + p) * 8 + b) * 8);
            const float* r1 = sRed + (((1 * 4 + p) * 8 + b) * 8);
            const float* r2 = sRed + (((2 * 4 + p) * 8 + b) * 8);
            const float* r3 = sRed + (((3 * 4 + p) * 8 + b) * 8);
            float gsum[6];
#pragma unroll
            for (int i = 0; i < 6; ++i)
                gsum[i] = (r0[i] + r1[i]) + (r2[i] + r3[i]);

            float2 hp = *(const float2*)(hrow + c0);
            // row order: jloc*3 + g; g: 0=r,1=z,2=n. bhh_n INSIDE the r* term.
            float rr0 = sigmoidf_(xv[0] + bh[0] + gsum[0]);
            float zz0 = sigmoidf_(xv[1] + bh[1] + gsum[1]);
            float nn0 = tanhf(xv[2] + rr0 * (gsum[2] + bh[2]));
            float rr1 = sigmoidf_(xv[3] + bh[3] + gsum[3]);
            float zz1 = sigmoidf_(xv[4] + bh[4] + gsum[4]);
            float nn1 = tanhf(xv[5] + rr1 * (gsum[5] + bh[5]));
            float h0 = (1.0f - zz0) * nn0 + zz0 * hp.x;
            float h1 = (1.0f - zz1) * nn1 + zz1 * hp.y;

            *(float2*)(out + ((size_t)b * TT + t) * HH + c0) = make_float2(h0, h1);
            float* hnext = g_h[(t + 1) & 1] + (size_t)b * HH + c0;
            asm volatile("st.global.cg.v2.f32 [%0], {%1, %2};"
                         :: "l"(hnext), "f"(h0), "f"(h1) : "memory");
        }

        // ---- grid barrier (release/acquire, distributed flags) ----
        __syncthreads();
        if (tid == 0) st_release_gpu(&g_flags[cta * FPAD], v0 + (unsigned)(t + 1));
        if (tid < NCTA) {
            while (ld_acquire_gpu(&g_flags[tid * FPAD]) - v0 < (unsigned)(t + 1)) { }
        }
        __syncthreads();

#pragma unroll
        for (int i = 0; i < 6; ++i) xv[i] = xnx[i];
    }
}

// ---------------- launcher ---------------------------------------------------
extern "C" void kernel_launch(void* const* d_in, const int* in_sizes, int n_in,
                              void* d_out, int out_size) {
    const float* x   = (const float*)d_in[0];
    const float* Wih = (const float*)d_in[1];
    const float* bih = (const float*)d_in[2];
    const float* Whh = (const float*)d_in[3];
    const float* bhh = (const float*)d_in[4];
    float* out = (float*)d_out;

    (void)in_sizes; (void)n_in; (void)out_size;

    // smem: W pack 96KB + h stage ~33KB + reduce 4KB
    const int kSmem = (4 * 512 * 6) * 8 + (BB * SHSTR) * 4 + (16 * 8 * 8) * 4;
    cudaFuncSetAttribute(gru_recurrent_kernel,
                         cudaFuncAttributeMaxDynamicSharedMemorySize, kSmem);

    dim3 g1(G3 / BN, (BB * TT) / BM);   // 24 x 256
    xproj_gemm_kernel<<<g1, 256>>>(x, Wih, bih);

    gru_recurrent_kernel<<<NCTA, NTHR, kSmem>>>(Whh, bhh, out);
}

// round 9
// speedup vs baseline: 1.0538x; 1.0538x over previous
#include <cuda_runtime.h>
#include <math.h>

#define BB 8
#define TT 2048
#define HH 1024
#define G3 3072
#define NCTA 128
#define NTHR 256
#define SHSTR 1032   // padded h row stride (floats)

typedef unsigned long long u64;

// ---------------- persistent scratch (device globals; zero-initialized) -----
__device__ float g_xproj[(size_t)TT * BB * G3];   // [t][b][3H]
__device__ float g_h[2][BB * HH];                 // double-buffered hidden state
__device__ u64 g_ctr;                             // barrier counter (monotonic)

__device__ __forceinline__ void red_release_add(u64* p, u64 v) {
    asm volatile("red.release.gpu.global.add.u64 [%0], %1;" :: "l"(p), "l"(v) : "memory");
}
__device__ __forceinline__ u64 ld_acquire_u64(const u64* p) {
    u64 v;
    asm volatile("ld.acquire.gpu.global.u64 %0, [%1];" : "=l"(v) : "l"(p) : "memory");
    return v;
}
// packed fp32x2 FMA (Blackwell)
__device__ __forceinline__ u64 fma2(u64 a, u64 b, u64 c) {
    u64 d;
    asm("fma.rn.f32x2 %0, %1, %2, %3;" : "=l"(d) : "l"(a), "l"(b), "l"(c));
    return d;
}
__device__ __forceinline__ float fold2(u64 v) {
    return __uint_as_float((unsigned)v) + __uint_as_float((unsigned)(v >> 32));
}
__device__ __forceinline__ float sigmoidf_(float v) {
    return 1.0f / (1.0f + expf(-v));
}
__device__ __forceinline__ void bar_named(int id, int nthr) {
    asm volatile("bar.sync %0, %1;" :: "r"(id), "r"(nthr) : "memory");
}

// ---------------- kernel A: x_proj = x @ W_ih^T + b_ih ----------------------
// (unchanged: conflict-free Bs map tx+16u; scatters to [t][b][3H])
#define BM 64
#define BN 128
#define BKK 16
#define APAD 18
#define BPAD 18

__global__ void __launch_bounds__(256, 2) xproj_gemm_kernel(
    const float* __restrict__ x,     // [b][t][h]
    const float* __restrict__ Wih,   // [3H, H]
    const float* __restrict__ bih)   // [3H]
{
    __shared__ float As[BM * APAD];
    __shared__ float Bs[BN * BPAD];

    const int tid = threadIdx.x;
    const int m0 = blockIdx.y * BM;
    const int n0 = blockIdx.x * BN;
    const int tx = tid & 15;
    const int ty = tid >> 4;

    const int ldRow = tid >> 2;
    const int ldCol = (tid & 3) * 4;

    const float* aPtr  = x   + (size_t)(m0 + ldRow) * HH + ldCol;
    const float* bPtr0 = Wih + (size_t)(n0 + ldRow) * HH + ldCol;
    const float* bPtr1 = Wih + (size_t)(n0 + ldRow + 64) * HH + ldCol;

    u64 acc[4][8];
#pragma unroll
    for (int i = 0; i < 4; ++i)
#pragma unroll
        for (int u = 0; u < 8; ++u) acc[i][u] = 0ull;

    for (int k0 = 0; k0 < HH; k0 += BKK) {
        float4 av  = *(const float4*)(aPtr  + k0);
        float4 bv0 = *(const float4*)(bPtr0 + k0);
        float4 bv1 = *(const float4*)(bPtr1 + k0);

        *(float2*)&As[ldRow * APAD + ldCol + 0] = make_float2(av.x, av.y);
        *(float2*)&As[ldRow * APAD + ldCol + 2] = make_float2(av.z, av.w);
        *(float2*)&Bs[ldRow * BPAD + ldCol + 0] = make_float2(bv0.x, bv0.y);
        *(float2*)&Bs[ldRow * BPAD + ldCol + 2] = make_float2(bv0.z, bv0.w);
        *(float2*)&Bs[(ldRow + 64) * BPAD + ldCol + 0] = make_float2(bv1.x, bv1.y);
        *(float2*)&Bs[(ldRow + 64) * BPAD + ldCol + 2] = make_float2(bv1.z, bv1.w);
        __syncthreads();

#pragma unroll
        for (int kk2 = 0; kk2 < BKK / 2; ++kk2) {
            u64 a2[4];
#pragma unroll
            for (int i = 0; i < 4; ++i)
                a2[i] = *(const u64*)&As[(ty * 4 + i) * APAD + kk2 * 2];
            u64 b2[8];
#pragma unroll
            for (int u = 0; u < 8; ++u)
                b2[u] = *(const u64*)&Bs[(tx + 16 * u) * BPAD + kk2 * 2];
#pragma unroll
            for (int i = 0; i < 4; ++i)
#pragma unroll
                for (int u = 0; u < 8; ++u)
                    acc[i][u] = fma2(a2[i], b2[u], acc[i][u]);
        }
        __syncthreads();
    }

#pragma unroll
    for (int i = 0; i < 4; ++i) {
        int m = m0 + ty * 4 + i;
        int b = m >> 11;
        int t = m & 2047;
        float* orow = g_xproj + ((size_t)t * BB + b) * G3 + n0;
#pragma unroll
        for (int u = 0; u < 8; ++u) {
            int c = tx + 16 * u;
            orow[c] = fold2(acc[i][u]) + __ldg(bih + n0 + c);
        }
    }
}

// ---------------- kernel B: persistent recurrence ---------------------------
// 256 threads = 8 warps. warp -> (p = wid&3, kh = wid>>2): col-pair {2p,2p+1},
// K-half kh. lane -> (b = lane&7, ks = lane>>3). W packed in smem; 6 W values
// per k-pair = 3 broadcast LDS.128. Each half-group stages ONLY its K-half of
// h and syncs on its own named barrier, so compute starts as soon as the
// group's half has landed. Grid barrier = single release-add counter.
__global__ void __launch_bounds__(NTHR, 1) gru_recurrent_kernel(
    const float* __restrict__ Whh,   // [3H, H]
    const float* __restrict__ bhh,   // [3H]
    float* __restrict__ out)         // [B, T, H]
{
    extern __shared__ float smem[];
    u64*   sWp  = (u64*)smem;                    // [4][512][6] u64 = 96KB
    float* sh   = smem + (4 * 512 * 6) * 2;      // [8][SHSTR]  ~33KB
    float* sRed = sh + BB * SHSTR;               // [8 warps][8 b][8] = 2KB

    const int tid  = threadIdx.x;
    const int cta  = blockIdx.x;
    const int wid  = tid >> 5;
    const int lane = tid & 31;
    const int p    = wid & 3;
    const int kh   = wid >> 2;        // K-half 0/1
    const int b    = lane & 7;
    const int ks   = lane >> 3;
    const int gtid = tid & 127;       // id within half-group
    const int barid = 1 + kh;         // named barrier per half-group

    // ---- pack W_hh: sWp[((pp*512 + kp)*6) + jloc*3 + g] = Whh k-pair ----
    for (int idx = tid; idx < 24 * 512; idx += NTHR) {
        int row = idx >> 9;          // 0..23
        int kp  = idx & 511;
        int jglob = row / 3;
        int g     = row % 3;
        int pp    = jglob >> 1;
        int jloc  = jglob & 1;
        const float* src = Whh + (size_t)(g * HH + cta * 8 + jglob) * HH + kp * 2;
        sWp[((pp * 512 + kp) * 6) + jloc * 3 + g] = *(const u64*)src;
    }
    __syncthreads();

    const int c0 = cta * 8 + 2 * p;
    float bh[6];
#pragma unroll
    for (int jl = 0; jl < 2; ++jl)
#pragma unroll
        for (int g = 0; g < 3; ++g)
            bh[jl * 3 + g] = bhh[g * HH + c0 + jl];

    const u64* wbase = sWp + (size_t)p * 512 * 6;
    const float* hrow = sh + b * SHSTR;

    // barrier base: counter is a multiple of NCTA*TT between launches; any
    // in-flight offset at read time is < NCTA, so the floor is exact.
    u64 craw = ld_acquire_u64(&g_ctr);
    const u64 cbase = craw - (craw % (u64)(NCTA * TT));

    // step-0 xproj prefetch (warps kh==0, lanes<8)
    float xv[6];
    if (kh == 0 && lane < 8) {
        const float* px = g_xproj + (size_t)b * G3;   // t=0
#pragma unroll
        for (int g = 0; g < 3; ++g) {
            float2 v = *(const float2*)(px + g * HH + c0);
            xv[0 * 3 + g] = v.x;
            xv[1 * 3 + g] = v.y;
        }
    }

    for (int t = 0; t < TT; ++t) {
        // ---- stage this group's K-half of h(t) into smem ----
        // half kh = float4 indices [kh*128, kh*128+128) of each b-row
        if (t == 0) {
            float4 z4 = make_float4(0.f, 0.f, 0.f, 0.f);
#pragma unroll
            for (int i = 0; i < 8; ++i) {
                int lin = gtid + i * 128;       // 0..1023
                int bb  = lin >> 7;
                int k4  = (lin & 127) + kh * 128;
                ((float4*)(sh + bb * SHSTR))[k4] = z4;
            }
        } else {
            const float* hin = g_h[t & 1];
#pragma unroll
            for (int i = 0; i < 8; ++i) {
                int lin = gtid + i * 128;
                int bb  = lin >> 7;
                int k4  = (lin & 127) + kh * 128;
                ((float4*)(sh + bb * SHSTR))[k4] =
                    __ldcg(((const float4*)(hin + (size_t)bb * HH)) + k4);
            }
        }

        // prefetch next step's xproj during compute (kh0 group only)
        float xnx[6] = {0.f, 0.f, 0.f, 0.f, 0.f, 0.f};
        if (kh == 0 && lane < 8 && t + 1 < TT) {
            const float* px = g_xproj + ((size_t)(t + 1) * BB + b) * G3;
#pragma unroll
            for (int g = 0; g < 3; ++g) {
                float2 v = *(const float2*)(px + g * HH + c0);
                xnx[0 * 3 + g] = v.x;
                xnx[1 * 3 + g] = v.y;
            }
        }

        // own half staged -> this group can start compute
        bar_named(barid, 128);

        // ---- partial dot products over this warp's K-half ----
        u64 acc0 = 0ull, acc1 = 0ull, acc2 = 0ull;
        u64 acc3 = 0ull, acc4 = 0ull, acc5 = 0ull;
        const int kp0 = kh * 256 + ks;
#pragma unroll 8
        for (int j = 0; j < 64; ++j) {
            int kp = kp0 + j * 4;
            const u64* wp = wbase + (size_t)kp * 6;
            ulonglong2 wA = *(const ulonglong2*)(wp + 0);
            ulonglong2 wB = *(const ulonglong2*)(wp + 2);
            ulonglong2 wC = *(const ulonglong2*)(wp + 4);
            u64 h2 = *(const u64*)(hrow + 2 * kp);
            acc0 = fma2(wA.x, h2, acc0);
            acc1 = fma2(wA.y, h2, acc1);
            acc2 = fma2(wB.x, h2, acc2);
            acc3 = fma2(wB.y, h2, acc3);
            acc4 = fma2(wC.x, h2, acc4);
            acc5 = fma2(wC.y, h2, acc5);
        }

        // fold + reduce over ks (lanes b, b+8, b+16, b+24)
        float s0 = fold2(acc0), s1 = fold2(acc1), s2 = fold2(acc2);
        float s3 = fold2(acc3), s4 = fold2(acc4), s5 = fold2(acc5);
#pragma unroll
        for (int off = 8; off <= 16; off <<= 1) {
            s0 += __shfl_xor_sync(0xffffffffu, s0, off);
            s1 += __shfl_xor_sync(0xffffffffu, s1, off);
            s2 += __shfl_xor_sync(0xffffffffu, s2, off);
            s3 += __shfl_xor_sync(0xffffffffu, s3, off);
            s4 += __shfl_xor_sync(0xffffffffu, s4, off);
            s5 += __shfl_xor_sync(0xffffffffu, s5, off);
        }

        // stage partials
        if (lane < 8) {
            float* dst = sRed + ((wid * 8 + b) * 8);
            dst[0] = s0; dst[1] = s1; dst[2] = s2;
            dst[3] = s3; dst[4] = s4; dst[5] = s5;
        }
        __syncthreads();

        // ---- combine K-halves + activations (warps kh==0, lanes<8) ----
        if (kh == 0 && lane < 8) {
            const float* r0 = sRed + ((p * 8 + b) * 8);          // kh=0 partial
            const float* r1 = sRed + (((4 + p) * 8 + b) * 8);    // kh=1 partial
            float gsum[6];
#pragma unroll
            for (int i = 0; i < 6; ++i) gsum[i] = r0[i] + r1[i];

            float2 hp = *(const float2*)(hrow + c0);
            // row order: jloc*3 + g; g: 0=r,1=z,2=n. bhh_n INSIDE the r* term.
            float rr0 = sigmoidf_(xv[0] + bh[0] + gsum[0]);
            float zz0 = sigmoidf_(xv[1] + bh[1] + gsum[1]);
            float nn0 = tanhf(xv[2] + rr0 * (gsum[2] + bh[2]));
            float rr1 = sigmoidf_(xv[3] + bh[3] + gsum[3]);
            float zz1 = sigmoidf_(xv[4] + bh[4] + gsum[4]);
            float nn1 = tanhf(xv[5] + rr1 * (gsum[5] + bh[5]));
            float h0 = (1.0f - zz0) * nn0 + zz0 * hp.x;
            float h1 = (1.0f - zz1) * nn1 + zz1 * hp.y;

            *(float2*)(out + ((size_t)b * TT + t) * HH + c0) = make_float2(h0, h1);
            float* hnext = g_h[(t + 1) & 1] + (size_t)b * HH + c0;
            asm volatile("st.global.cg.v2.f32 [%0], {%1, %2};"
                         :: "l"(hnext), "f"(h0), "f"(h1) : "memory");
        }

        // ---- grid barrier: single release-add counter, tid0 polls 1 line ----
        __syncthreads();
        if (tid == 0) {
            red_release_add(&g_ctr, 1ull);
            const u64 target = cbase + (u64)NCTA * (u64)(t + 1);
            while (ld_acquire_u64(&g_ctr) < target) { }
        }
        __syncthreads();

#pragma unroll
        for (int i = 0; i < 6; ++i) xv[i] = xnx[i];
    }
    // counter ends at cbase + NCTA*TT (multiple of NCTA*TT) -> replay-safe
}

// ---------------- launcher ---------------------------------------------------
extern "C" void kernel_launch(void* const* d_in, const int* in_sizes, int n_in,
                              void* d_out, int out_size) {
    const float* x   = (const float*)d_in[0];
    const float* Wih = (const float*)d_in[1];
    const float* bih = (const float*)d_in[2];
    const float* Whh = (const float*)d_in[3];
    const float* bhh = (const float*)d_in[4];
    float* out = (float*)d_out;

    (void)in_sizes; (void)n_in; (void)out_size;

    // smem: W pack 96KB + h stage ~33KB + reduce 2KB
    const int kSmem = (4 * 512 * 6) * 8 + (BB * SHSTR) * 4 + (8 * 8 * 8) * 4;
    cudaFuncSetAttribute(gru_recurrent_kernel,
                         cudaFuncAttributeMaxDynamicSharedMemorySize, kSmem);

    dim3 g1(G3 / BN, (BB * TT) / BM);   // 24 x 256
    xproj_gemm_kernel<<<g1, 256>>>(x, Wih, bih);

    gru_recurrent_kernel<<<NCTA, NTHR, kSmem>>>(Whh, bhh, out);
}

// round 10
// speedup vs baseline: 1.0680x; 1.0135x over previous
#include <cuda_runtime.h>
#include <math.h>

#define BB 8
#define TT 2048
#define HH 1024
#define G3 3072
#define NCTA 128
#define NTHR 256
#define SHSTR 1032   // padded h row stride (floats)
#define NGRP 8       // barrier counter groups (16 CTAs each)

typedef unsigned long long u64;

// ---------------- persistent scratch (device globals; zero-initialized) -----
__device__ float g_xproj[(size_t)TT * BB * G3];   // [t][b][3H]
__device__ float g_h[2][BB * HH];                 // double-buffered hidden state
__device__ u64 g_ctrs[NGRP * 16];                 // 8 counters, 128B apart

__device__ __forceinline__ void red_release_add(u64* p, u64 v) {
    asm volatile("red.release.gpu.global.add.u64 [%0], %1;" :: "l"(p), "l"(v) : "memory");
}
__device__ __forceinline__ u64 ld_acquire_u64(const u64* p) {
    u64 v;
    asm volatile("ld.acquire.gpu.global.u64 %0, [%1];" : "=l"(v) : "l"(p) : "memory");
    return v;
}
// packed fp32x2 FMA (Blackwell)
__device__ __forceinline__ u64 fma2(u64 a, u64 b, u64 c) {
    u64 d;
    asm("fma.rn.f32x2 %0, %1, %2, %3;" : "=l"(d) : "l"(a), "l"(b), "l"(c));
    return d;
}
__device__ __forceinline__ float fold2(u64 v) {
    return __uint_as_float((unsigned)v) + __uint_as_float((unsigned)(v >> 32));
}
__device__ __forceinline__ float tanhapx(float x) {
    float y;
    asm("tanh.approx.f32 %0, %1;" : "=f"(y) : "f"(x));
    return y;
}
__device__ __forceinline__ float sigapx(float x) {
    return fmaf(0.5f, tanhapx(0.5f * x), 0.5f);
}
__device__ __forceinline__ void bar_named(int id, int nthr) {
    asm volatile("bar.sync %0, %1;" :: "r"(id), "r"(nthr) : "memory");
}

// ---------------- kernel A: x_proj = x @ W_ih^T + b_ih ----------------------
// Conflict-free Bs map (cols tx+16u); scatters to [t][b][3H].
// Register prefetch of the next k-tile hides per-tile L2 latency.
#define BM 64
#define BN 128
#define BKK 16
#define APAD 18
#define BPAD 18

__global__ void __launch_bounds__(256, 2) xproj_gemm_kernel(
    const float* __restrict__ x,     // [b][t][h]
    const float* __restrict__ Wih,   // [3H, H]
    const float* __restrict__ bih)   // [3H]
{
    __shared__ float As[BM * APAD];
    __shared__ float Bs[BN * BPAD];

    const int tid = threadIdx.x;
    const int m0 = blockIdx.y * BM;
    const int n0 = blockIdx.x * BN;
    const int tx = tid & 15;
    const int ty = tid >> 4;

    const int ldRow = tid >> 2;
    const int ldCol = (tid & 3) * 4;

    const float* aPtr  = x   + (size_t)(m0 + ldRow) * HH + ldCol;
    const float* bPtr0 = Wih + (size_t)(n0 + ldRow) * HH + ldCol;
    const float* bPtr1 = Wih + (size_t)(n0 + ldRow + 64) * HH + ldCol;

    u64 acc[4][8];
#pragma unroll
    for (int i = 0; i < 4; ++i)
#pragma unroll
        for (int u = 0; u < 8; ++u) acc[i][u] = 0ull;

    float4 av  = *(const float4*)(aPtr);
    float4 bv0 = *(const float4*)(bPtr0);
    float4 bv1 = *(const float4*)(bPtr1);

    for (int k0 = 0; k0 < HH; k0 += BKK) {
        *(float2*)&As[ldRow * APAD + ldCol + 0] = make_float2(av.x, av.y);
        *(float2*)&As[ldRow * APAD + ldCol + 2] = make_float2(av.z, av.w);
        *(float2*)&Bs[ldRow * BPAD + ldCol + 0] = make_float2(bv0.x, bv0.y);
        *(float2*)&Bs[ldRow * BPAD + ldCol + 2] = make_float2(bv0.z, bv0.w);
        *(float2*)&Bs[(ldRow + 64) * BPAD + ldCol + 0] = make_float2(bv1.x, bv1.y);
        *(float2*)&Bs[(ldRow + 64) * BPAD + ldCol + 2] = make_float2(bv1.z, bv1.w);
        __syncthreads();

        if (k0 + BKK < HH) {       // prefetch next tile while computing
            av  = *(const float4*)(aPtr  + k0 + BKK);
            bv0 = *(const float4*)(bPtr0 + k0 + BKK);
            bv1 = *(const float4*)(bPtr1 + k0 + BKK);
        }

#pragma unroll
        for (int kk2 = 0; kk2 < BKK / 2; ++kk2) {
            u64 a2[4];
#pragma unroll
            for (int i = 0; i < 4; ++i)
                a2[i] = *(const u64*)&As[(ty * 4 + i) * APAD + kk2 * 2];
            u64 b2[8];
#pragma unroll
            for (int u = 0; u < 8; ++u)
                b2[u] = *(const u64*)&Bs[(tx + 16 * u) * BPAD + kk2 * 2];
#pragma unroll
            for (int i = 0; i < 4; ++i)
#pragma unroll
                for (int u = 0; u < 8; ++u)
                    acc[i][u] = fma2(a2[i], b2[u], acc[i][u]);
        }
        __syncthreads();
    }

#pragma unroll
    for (int i = 0; i < 4; ++i) {
        int m = m0 + ty * 4 + i;
        int b = m >> 11;
        int t = m & 2047;
        float* orow = g_xproj + ((size_t)t * BB + b) * G3 + n0;
#pragma unroll
        for (int u = 0; u < 8; ++u) {
            int c = tx + 16 * u;
            orow[c] = fold2(acc[i][u]) + __ldg(bih + n0 + c);
        }
    }
}

// ---------------- kernel B: persistent recurrence ---------------------------
// 256 threads = 8 warps. warp -> (p = wid&3, kh = wid>>2). lane -> (b, ks).
// Grid barrier: 8 split counters (16 CTAs each). kh0 group: finalize ->
// bar(3) [orders h stores] -> tid0 release-add -> warp0 lanes<8 poll all 8
// counters -> bar(3) -> stage. kh1 group: warp4 lanes<8 poll -> bar(4) ->
// stage. hp (own cols' prev h) lives in finalize-lane registers.
__global__ void __launch_bounds__(NTHR, 1) gru_recurrent_kernel(
    const float* __restrict__ Whh,   // [3H, H]
    const float* __restrict__ bhh,   // [3H]
    float* __restrict__ out)         // [B, T, H]
{
    extern __shared__ float smem[];
    u64*   sWp  = (u64*)smem;                    // [4][512][6] u64 = 96KB
    float* sh   = smem + (4 * 512 * 6) * 2;      // [8][SHSTR]  ~33KB
    float* sRed = sh + BB * SHSTR;               // [8 warps][8 b][8] = 2KB

    const int tid  = threadIdx.x;
    const int cta  = blockIdx.x;
    const int wid  = tid >> 5;
    const int lane = tid & 31;
    const int p    = wid & 3;
    const int kh   = wid >> 2;        // K-half 0/1
    const int b    = lane & 7;
    const int ks   = lane >> 3;
    const int gtid = tid & 127;       // id within half-group
    const int grp  = cta >> 4;        // counter group 0..7

    // ---- pack W_hh: sWp[((pp*512 + kp)*6) + jloc*3 + g] = Whh k-pair ----
    for (int idx = tid; idx < 24 * 512; idx += NTHR) {
        int row = idx >> 9;
        int kp  = idx & 511;
        int jglob = row / 3;
        int g     = row % 3;
        int pp    = jglob >> 1;
        int jloc  = jglob & 1;
        const float* src = Whh + (size_t)(g * HH + cta * 8 + jglob) * HH + kp * 2;
        sWp[((pp * 512 + kp) * 6) + jloc * 3 + g] = *(const u64*)src;
    }
    __syncthreads();

    const int c0 = cta * 8 + 2 * p;
    float bh[6];
#pragma unroll
    for (int jl = 0; jl < 2; ++jl)
#pragma unroll
        for (int g = 0; g < 3; ++g)
            bh[jl * 3 + g] = bhh[g * HH + c0 + jl];

    const u64* wbase = sWp + (size_t)p * 512 * 6;
    const float* hrow = sh + b * SHSTR;

    // poller base per counter (monotonic; counters are multiples of 16*TT at
    // launch boundaries, in-flight offset < 16*TT at read time -> floor exact)
    const bool poller = (lane < 8) && (wid == 0 || wid == 4);
    u64 mybase = 0;
    if (poller) {
        u64 craw = ld_acquire_u64(&g_ctrs[lane * 16]);
        mybase = craw - (craw % (u64)(16 * TT));
    }

    // previous-h registers for this finalize lane's own columns
    float hp0 = 0.f, hp1 = 0.f;

    // step-0 xproj prefetch (kh==0 lanes<8)
    float xv[6];
    if (kh == 0 && lane < 8) {
        const float* px = g_xproj + (size_t)b * G3;   // t=0
#pragma unroll
        for (int g = 0; g < 3; ++g) {
            float2 v = *(const float2*)(px + g * HH + c0);
            xv[0 * 3 + g] = v.x;
            xv[1 * 3 + g] = v.y;
        }
    }

    for (int t = 0; t < TT; ++t) {
        // ---- stage this group's K-half of h(t) into smem ----
        if (t == 0) {
            float4 z4 = make_float4(0.f, 0.f, 0.f, 0.f);
#pragma unroll
            for (int i = 0; i < 8; ++i) {
                int lin = gtid + i * 128;
                int bb  = lin >> 7;
                int k4  = (lin & 127) + kh * 128;
                ((float4*)(sh + bb * SHSTR))[k4] = z4;
            }
        } else {
            const float* hin = g_h[t & 1];
#pragma unroll
            for (int i = 0; i < 8; ++i) {
                int lin = gtid + i * 128;
                int bb  = lin >> 7;
                int k4  = (lin & 127) + kh * 128;
                ((float4*)(sh + bb * SHSTR))[k4] =
                    __ldcg(((const float4*)(hin + (size_t)bb * HH)) + k4);
            }
        }

        // prefetch next step's xproj (in flight through compute)
        float xnx[6] = {0.f, 0.f, 0.f, 0.f, 0.f, 0.f};
        if (kh == 0 && lane < 8 && t + 1 < TT) {
            const float* px = g_xproj + ((size_t)(t + 1) * BB + b) * G3;
#pragma unroll
            for (int g = 0; g < 3; ++g) {
                float2 v = *(const float2*)(px + g * HH + c0);
                xnx[0 * 3 + g] = v.x;
                xnx[1 * 3 + g] = v.y;
            }
        }

        bar_named(1 + kh, 128);   // own half staged -> group computes

        // ---- partial dot products over this warp's K-half ----
        u64 acc0 = 0ull, acc1 = 0ull, acc2 = 0ull;
        u64 acc3 = 0ull, acc4 = 0ull, acc5 = 0ull;
        const int kp0 = kh * 256 + ks;
#pragma unroll 8
        for (int j = 0; j < 64; ++j) {
            int kp = kp0 + j * 4;
            const u64* wp = wbase + (size_t)kp * 6;
            ulonglong2 wA = *(const ulonglong2*)(wp + 0);
            ulonglong2 wB = *(const ulonglong2*)(wp + 2);
            ulonglong2 wC = *(const ulonglong2*)(wp + 4);
            u64 h2 = *(const u64*)(hrow + 2 * kp);
            acc0 = fma2(wA.x, h2, acc0);
            acc1 = fma2(wA.y, h2, acc1);
            acc2 = fma2(wB.x, h2, acc2);
            acc3 = fma2(wB.y, h2, acc3);
            acc4 = fma2(wC.x, h2, acc4);
            acc5 = fma2(wC.y, h2, acc5);
        }

        // fold + reduce over ks
        float s0 = fold2(acc0), s1 = fold2(acc1), s2 = fold2(acc2);
        float s3 = fold2(acc3), s4 = fold2(acc4), s5 = fold2(acc5);
#pragma unroll
        for (int off = 8; off <= 16; off <<= 1) {
            s0 += __shfl_xor_sync(0xffffffffu, s0, off);
            s1 += __shfl_xor_sync(0xffffffffu, s1, off);
            s2 += __shfl_xor_sync(0xffffffffu, s2, off);
            s3 += __shfl_xor_sync(0xffffffffu, s3, off);
            s4 += __shfl_xor_sync(0xffffffffu, s4, off);
            s5 += __shfl_xor_sync(0xffffffffu, s5, off);
        }

        if (lane < 8) {
            float* dst = sRed + ((wid * 8 + b) * 8);
            dst[0] = s0; dst[1] = s1; dst[2] = s2;
            dst[3] = s3; dst[4] = s4; dst[5] = s5;
        }
        __syncthreads();   // (A): all compute + sRed done; sh is dead

        if (kh == 0) {
            if (lane < 8) {
                const float* r0 = sRed + ((p * 8 + b) * 8);
                const float* r1 = sRed + (((4 + p) * 8 + b) * 8);
                float gsum[6];
#pragma unroll
                for (int i = 0; i < 6; ++i) gsum[i] = r0[i] + r1[i];

                // g: 0=r,1=z,2=n; bhh_n sits INSIDE the r* term.
                float rr0 = sigapx(xv[0] + bh[0] + gsum[0]);
                float zz0 = sigapx(xv[1] + bh[1] + gsum[1]);
                float nn0 = tanhapx(xv[2] + rr0 * (gsum[2] + bh[2]));
                float rr1 = sigapx(xv[3] + bh[3] + gsum[3]);
                float zz1 = sigapx(xv[4] + bh[4] + gsum[4]);
                float nn1 = tanhapx(xv[5] + rr1 * (gsum[5] + bh[5]));
                float h0 = (1.0f - zz0) * nn0 + zz0 * hp0;
                float h1 = (1.0f - zz1) * nn1 + zz1 * hp1;
                hp0 = h0; hp1 = h1;

                *(float2*)(out + ((size_t)b * TT + t) * HH + c0) = make_float2(h0, h1);
                float* hnext = g_h[(t + 1) & 1] + (size_t)b * HH + c0;
                asm volatile("st.global.cg.v2.f32 [%0], {%1, %2};"
                             :: "l"(hnext), "f"(h0), "f"(h1) : "memory");
            }
            bar_named(3, 128);      // orders h stores before the release-add
            if (tid == 0) red_release_add(&g_ctrs[grp * 16], 1ull);
            if (wid == 0 && lane < 8) {
                const u64 tgt = mybase + (u64)16 * (u64)(t + 1);
                while (ld_acquire_u64(&g_ctrs[lane * 16]) < tgt) { }
            }
            bar_named(3, 128);      // poll result -> whole kh0 group
        } else {
            if (wid == 4 && lane < 8) {
                const u64 tgt = mybase + (u64)16 * (u64)(t + 1);
                while (ld_acquire_u64(&g_ctrs[lane * 16]) < tgt) { }
            }
            bar_named(4, 128);      // poll result -> whole kh1 group
        }

#pragma unroll
        for (int i = 0; i < 6; ++i) xv[i] = xnx[i];
    }
    // counters end at base + 16*TT (multiple of 16*TT) -> replay-safe
}

// ---------------- launcher ---------------------------------------------------
extern "C" void kernel_launch(void* const* d_in, const int* in_sizes, int n_in,
                              void* d_out, int out_size) {
    const float* x   = (const float*)d_in[0];
    const float* Wih = (const float*)d_in[1];
    const float* bih = (const float*)d_in[2];
    const float* Whh = (const float*)d_in[3];
    const float* bhh = (const float*)d_in[4];
    float* out = (float*)d_out;

    (void)in_sizes; (void)n_in; (void)out_size;

    // smem: W pack 96KB + h stage ~33KB + reduce 2KB
    const int kSmem = (4 * 512 * 6) * 8 + (BB * SHSTR) * 4 + (8 * 8 * 8) * 4;
    cudaFuncSetAttribute(gru_recurrent_kernel,
                         cudaFuncAttributeMaxDynamicSharedMemorySize, kSmem);

    dim3 g1(G3 / BN, (BB * TT) / BM);   // 24 x 256
    xproj_gemm_kernel<<<g1, 256>>>(x, Wih, bih);

    gru_recurrent_kernel<<<NCTA, NTHR, kSmem>>>(Whh, bhh, out);
}

// round 11
// speedup vs baseline: 1.1236x; 1.0520x over previous
#include <cuda_runtime.h>
#include <math.h>

#define BB 8
#define TT 2048
#define HH 1024
#define G3 3072
#define NCTA 128
#define NTHR 256
#define SHSTR 1040   // h row stride (floats); SHSTR/2 % 16 == 8 -> 2-phase LDS.64 floor
#define NGRP 8       // barrier counter groups (16 CTAs each)

typedef unsigned long long u64;

// ---------------- persistent scratch (device globals; zero-initialized) -----
__device__ float g_xproj[(size_t)TT * BB * G3];   // [t][b][3H]
__device__ float g_h[2][BB * HH];                 // double-buffered hidden state
__device__ u64 g_ctrs[NGRP * 16];                 // 8 counters, 128B apart

__device__ __forceinline__ void red_release_add(u64* p, u64 v) {
    asm volatile("red.release.gpu.global.add.u64 [%0], %1;" :: "l"(p), "l"(v) : "memory");
}
__device__ __forceinline__ u64 ld_acquire_u64(const u64* p) {
    u64 v;
    asm volatile("ld.acquire.gpu.global.u64 %0, [%1];" : "=l"(v) : "l"(p) : "memory");
    return v;
}
// packed fp32x2 FMA (Blackwell)
__device__ __forceinline__ u64 fma2(u64 a, u64 b, u64 c) {
    u64 d;
    asm("fma.rn.f32x2 %0, %1, %2, %3;" : "=l"(d) : "l"(a), "l"(b), "l"(c));
    return d;
}
__device__ __forceinline__ float fold2(u64 v) {
    return __uint_as_float((unsigned)v) + __uint_as_float((unsigned)(v >> 32));
}
__device__ __forceinline__ float tanhapx(float x) {
    float y;
    asm("tanh.approx.f32 %0, %1;" : "=f"(y) : "f"(x));
    return y;
}
__device__ __forceinline__ float sigapx(float x) {
    return fmaf(0.5f, tanhapx(0.5f * x), 0.5f);
}
__device__ __forceinline__ void bar_named(int id, int nthr) {
    asm volatile("bar.sync %0, %1;" :: "r"(id), "r"(nthr) : "memory");
}

// ---------------- kernel A: x_proj = x @ W_ih^T + b_ih ----------------------
// (unchanged from R9: conflict-free Bs map tx+16u, next-tile register prefetch)
#define BM 64
#define BN 128
#define BKK 16
#define APAD 18
#define BPAD 18

__global__ void __launch_bounds__(256, 2) xproj_gemm_kernel(
    const float* __restrict__ x,     // [b][t][h]
    const float* __restrict__ Wih,   // [3H, H]
    const float* __restrict__ bih)   // [3H]
{
    __shared__ float As[BM * APAD];
    __shared__ float Bs[BN * BPAD];

    const int tid = threadIdx.x;
    const int m0 = blockIdx.y * BM;
    const int n0 = blockIdx.x * BN;
    const int tx = tid & 15;
    const int ty = tid >> 4;

    const int ldRow = tid >> 2;
    const int ldCol = (tid & 3) * 4;

    const float* aPtr  = x   + (size_t)(m0 + ldRow) * HH + ldCol;
    const float* bPtr0 = Wih + (size_t)(n0 + ldRow) * HH + ldCol;
    const float* bPtr1 = Wih + (size_t)(n0 + ldRow + 64) * HH + ldCol;

    u64 acc[4][8];
#pragma unroll
    for (int i = 0; i < 4; ++i)
#pragma unroll
        for (int u = 0; u < 8; ++u) acc[i][u] = 0ull;

    float4 av  = *(const float4*)(aPtr);
    float4 bv0 = *(const float4*)(bPtr0);
    float4 bv1 = *(const float4*)(bPtr1);

    for (int k0 = 0; k0 < HH; k0 += BKK) {
        *(float2*)&As[ldRow * APAD + ldCol + 0] = make_float2(av.x, av.y);
        *(float2*)&As[ldRow * APAD + ldCol + 2] = make_float2(av.z, av.w);
        *(float2*)&Bs[ldRow * BPAD + ldCol + 0] = make_float2(bv0.x, bv0.y);
        *(float2*)&Bs[ldRow * BPAD + ldCol + 2] = make_float2(bv0.z, bv0.w);
        *(float2*)&Bs[(ldRow + 64) * BPAD + ldCol + 0] = make_float2(bv1.x, bv1.y);
        *(float2*)&Bs[(ldRow + 64) * BPAD + ldCol + 2] = make_float2(bv1.z, bv1.w);
        __syncthreads();

        if (k0 + BKK < HH) {
            av  = *(const float4*)(aPtr  + k0 + BKK);
            bv0 = *(const float4*)(bPtr0 + k0 + BKK);
            bv1 = *(const float4*)(bPtr1 + k0 + BKK);
        }

#pragma unroll
        for (int kk2 = 0; kk2 < BKK / 2; ++kk2) {
            u64 a2[4];
#pragma unroll
            for (int i = 0; i < 4; ++i)
                a2[i] = *(const u64*)&As[(ty * 4 + i) * APAD + kk2 * 2];
            u64 b2[8];
#pragma unroll
            for (int u = 0; u < 8; ++u)
                b2[u] = *(const u64*)&Bs[(tx + 16 * u) * BPAD + kk2 * 2];
#pragma unroll
            for (int i = 0; i < 4; ++i)
#pragma unroll
                for (int u = 0; u < 8; ++u)
                    acc[i][u] = fma2(a2[i], b2[u], acc[i][u]);
        }
        __syncthreads();
    }

#pragma unroll
    for (int i = 0; i < 4; ++i) {
        int m = m0 + ty * 4 + i;
        int b = m >> 11;
        int t = m & 2047;
        float* orow = g_xproj + ((size_t)t * BB + b) * G3 + n0;
#pragma unroll
        for (int u = 0; u < 8; ++u) {
            int c = tx + 16 * u;
            orow[c] = fold2(acc[i][u]) + __ldg(bih + n0 + c);
        }
    }
}

// ---------------- kernel B: persistent recurrence ---------------------------
// 256 threads = 8 warps. warp -> (p = wid&3, kh = wid>>2): col-pair {2p,2p+1},
// K-half kh. lane -> (b4 = lane>>3 in 0..3, ks8 = lane&7): lane covers batches
// {b4, b4+4} and k-pairs kp = kh*256 + ks8 + 8j. W loads: 3x LDS.128 with 8
// distinct kp -> 128B/phase dense (1 phase each). h loads: 2x LDS.64 at the
// 2-phase floor (SHSTR/2 % 16 == 8). 12 accumulators/lane; reduce over ks8.
__global__ void __launch_bounds__(NTHR, 1) gru_recurrent_kernel(
    const float* __restrict__ Whh,   // [3H, H]
    const float* __restrict__ bhh,   // [3H]
    float* __restrict__ out)         // [B, T, H]
{
    extern __shared__ float smem[];
    u64*   sWp  = (u64*)smem;                    // [4][512][6] u64 = 96KB
    float* sh   = smem + (4 * 512 * 6) * 2;      // [8][SHSTR]  32.5KB
    float* sRed = sh + BB * SHSTR;               // [8 warps][4 b4][12] = 1.5KB

    const int tid  = threadIdx.x;
    const int cta  = blockIdx.x;
    const int wid  = tid >> 5;
    const int lane = tid & 31;
    const int p    = wid & 3;
    const int kh   = wid >> 2;        // K-half 0/1
    const int b4   = lane >> 3;       // 0..3
    const int ks8  = lane & 7;        // 0..7
    const int gtid = tid & 127;       // id within half-group
    const int grp  = cta >> 4;        // counter group 0..7

    // ---- pack W_hh: sWp[((pp*512 + kp)*6) + jloc*3 + g] = Whh k-pair ----
    for (int idx = tid; idx < 24 * 512; idx += NTHR) {
        int row = idx >> 9;
        int kp  = idx & 511;
        int jglob = row / 3;
        int g     = row % 3;
        int pp    = jglob >> 1;
        int jloc  = jglob & 1;
        const float* src = Whh + (size_t)(g * HH + cta * 8 + jglob) * HH + kp * 2;
        sWp[((pp * 512 + kp) * 6) + jloc * 3 + g] = *(const u64*)src;
    }
    __syncthreads();

    const int c0 = cta * 8 + 2 * p;
    float bh[6];
#pragma unroll
    for (int jl = 0; jl < 2; ++jl)
#pragma unroll
        for (int g = 0; g < 3; ++g)
            bh[jl * 3 + g] = bhh[g * HH + c0 + jl];

    const u64* wbase = sWp + (size_t)p * 512 * 6;
    const float* hrowA = sh + b4 * SHSTR;          // batch b4
    const float* hrowB = sh + (b4 + 4) * SHSTR;    // batch b4+4

    // poller base per counter (monotonic; exact floor at launch boundaries)
    const bool poller = (lane < 8) && (wid == 0 || wid == 4);
    u64 mybase = 0;
    if (poller) {
        u64 craw = ld_acquire_u64(&g_ctrs[lane * 16]);
        mybase = craw - (craw % (u64)(16 * TT));
    }

    // previous-h registers for this finalize lane's own columns
    float hp0 = 0.f, hp1 = 0.f;

    // step-0 xproj prefetch (kh==0 lanes<8; finalize lane b = lane)
    const int fb = lane & 7;          // finalize batch for lanes<8 (== lane)
    float xv[6];
    if (kh == 0 && lane < 8) {
        const float* px = g_xproj + (size_t)fb * G3;   // t=0
#pragma unroll
        for (int g = 0; g < 3; ++g) {
            float2 v = *(const float2*)(px + g * HH + c0);
            xv[0 * 3 + g] = v.x;
            xv[1 * 3 + g] = v.y;
        }
    }

    for (int t = 0; t < TT; ++t) {
        // ---- stage this group's K-half of h(t) into smem ----
        if (t == 0) {
            float4 z4 = make_float4(0.f, 0.f, 0.f, 0.f);
#pragma unroll
            for (int i = 0; i < 8; ++i) {
                int lin = gtid + i * 128;
                int bb  = lin >> 7;
                int k4  = (lin & 127) + kh * 128;
                ((float4*)(sh + bb * SHSTR))[k4] = z4;
            }
        } else {
            const float* hin = g_h[t & 1];
#pragma unroll
            for (int i = 0; i < 8; ++i) {
                int lin = gtid + i * 128;
                int bb  = lin >> 7;
                int k4  = (lin & 127) + kh * 128;
                ((float4*)(sh + bb * SHSTR))[k4] =
                    __ldcg(((const float4*)(hin + (size_t)bb * HH)) + k4);
            }
        }

        // prefetch next step's xproj (in flight through compute)
        float xnx[6] = {0.f, 0.f, 0.f, 0.f, 0.f, 0.f};
        if (kh == 0 && lane < 8 && t + 1 < TT) {
            const float* px = g_xproj + ((size_t)(t + 1) * BB + fb) * G3;
#pragma unroll
            for (int g = 0; g < 3; ++g) {
                float2 v = *(const float2*)(px + g * HH + c0);
                xnx[0 * 3 + g] = v.x;
                xnx[1 * 3 + g] = v.y;
            }
        }

        bar_named(1 + kh, 128);   // own half staged -> group computes

        // ---- partial dot products: 6 (jloc x gate) x 2 batches ----
        u64 aA0 = 0ull, aA1 = 0ull, aA2 = 0ull, aA3 = 0ull, aA4 = 0ull, aA5 = 0ull;
        u64 aB0 = 0ull, aB1 = 0ull, aB2 = 0ull, aB3 = 0ull, aB4 = 0ull, aB5 = 0ull;
        const int kp0 = kh * 256 + ks8;
#pragma unroll 4
        for (int j = 0; j < 32; ++j) {
            int kp = kp0 + j * 8;
            const u64* wp = wbase + (size_t)kp * 6;
            ulonglong2 wA = *(const ulonglong2*)(wp + 0);   // jl0g0, jl0g1
            ulonglong2 wB = *(const ulonglong2*)(wp + 2);   // jl0g2, jl1g0
            ulonglong2 wC = *(const ulonglong2*)(wp + 4);   // jl1g1, jl1g2
            u64 hA = *(const u64*)(hrowA + 2 * kp);
            u64 hB = *(const u64*)(hrowB + 2 * kp);
            aA0 = fma2(wA.x, hA, aA0);  aB0 = fma2(wA.x, hB, aB0);
            aA1 = fma2(wA.y, hA, aA1);  aB1 = fma2(wA.y, hB, aB1);
            aA2 = fma2(wB.x, hA, aA2);  aB2 = fma2(wB.x, hB, aB2);
            aA3 = fma2(wB.y, hA, aA3);  aB3 = fma2(wB.y, hB, aB3);
            aA4 = fma2(wC.x, hA, aA4);  aB4 = fma2(wC.x, hB, aB4);
            aA5 = fma2(wC.y, hA, aA5);  aB5 = fma2(wC.y, hB, aB5);
        }

        // fold + reduce over ks8 (shfl within 8-lane groups)
        float s[12];
        s[0] = fold2(aA0); s[1] = fold2(aA1); s[2]  = fold2(aA2);
        s[3] = fold2(aA3); s[4] = fold2(aA4); s[5]  = fold2(aA5);
        s[6] = fold2(aB0); s[7] = fold2(aB1); s[8]  = fold2(aB2);
        s[9] = fold2(aB3); s[10] = fold2(aB4); s[11] = fold2(aB5);
#pragma unroll
        for (int off = 1; off <= 4; off <<= 1) {
#pragma unroll
            for (int i = 0; i < 12; ++i)
                s[i] += __shfl_xor_sync(0xffffffffu, s[i], off);
        }

        // stage partials: one writer lane per (warp, b4)
        if (ks8 == 0) {
            float* dst = sRed + ((wid * 4 + b4) * 12);
#pragma unroll
            for (int i = 0; i < 12; ++i) dst[i] = s[i];
        }
        __syncthreads();   // all compute + sRed done; sh is dead

        if (kh == 0) {
            if (lane < 8) {
                const int rb4 = fb & 3;
                const int off6 = (fb >> 2) * 6;   // batch-half select
                const float* r0 = sRed + ((p * 4 + rb4) * 12) + off6;
                const float* r1 = sRed + (((4 + p) * 4 + rb4) * 12) + off6;
                float gsum[6];
#pragma unroll
                for (int i = 0; i < 6; ++i) gsum[i] = r0[i] + r1[i];

                // order jloc*3+g; g: 0=r,1=z,2=n; bhh_n sits INSIDE the r* term
                float rr0 = sigapx(xv[0] + bh[0] + gsum[0]);
                float zz0 = sigapx(xv[1] + bh[1] + gsum[1]);
                float nn0 = tanhapx(xv[2] + rr0 * (gsum[2] + bh[2]));
                float rr1 = sigapx(xv[3] + bh[3] + gsum[3]);
                float zz1 = sigapx(xv[4] + bh[4] + gsum[4]);
                float nn1 = tanhapx(xv[5] + rr1 * (gsum[5] + bh[5]));
                float h0 = (1.0f - zz0) * nn0 + zz0 * hp0;
                float h1 = (1.0f - zz1) * nn1 + zz1 * hp1;
                hp0 = h0; hp1 = h1;

                *(float2*)(out + ((size_t)fb * TT + t) * HH + c0) = make_float2(h0, h1);
                float* hnext = g_h[(t + 1) & 1] + (size_t)fb * HH + c0;
                asm volatile("st.global.cg.v2.f32 [%0], {%1, %2};"
                             :: "l"(hnext), "f"(h0), "f"(h1) : "memory");
            }
            bar_named(3, 128);      // orders h stores before the release-add
            if (tid == 0) red_release_add(&g_ctrs[grp * 16], 1ull);
            if (wid == 0 && lane < 8) {
                const u64 tgt = mybase + (u64)16 * (u64)(t + 1);
                while (ld_acquire_u64(&g_ctrs[lane * 16]) < tgt) { }
            }
            bar_named(3, 128);      // poll result -> whole kh0 group
        } else {
            if (wid == 4 && lane < 8) {
                const u64 tgt = mybase + (u64)16 * (u64)(t + 1);
                while (ld_acquire_u64(&g_ctrs[lane * 16]) < tgt) { }
            }
            bar_named(4, 128);      // poll result -> whole kh1 group
        }

#pragma unroll
        for (int i = 0; i < 6; ++i) xv[i] = xnx[i];
    }
    // counters end at base + 16*TT (multiple of 16*TT) -> replay-safe
}

// ---------------- launcher ---------------------------------------------------
extern "C" void kernel_launch(void* const* d_in, const int* in_sizes, int n_in,
                              void* d_out, int out_size) {
    const float* x   = (const float*)d_in[0];
    const float* Wih = (const float*)d_in[1];
    const float* bih = (const float*)d_in[2];
    const float* Whh = (const float*)d_in[3];
    const float* bhh = (const float*)d_in[4];
    float* out = (float*)d_out;

    (void)in_sizes; (void)n_in; (void)out_size;

    // smem: W pack 96KB + h stage 32.5KB + reduce 1.5KB
    const int kSmem = (4 * 512 * 6) * 8 + (BB * SHSTR) * 4 + (8 * 4 * 12) * 4;
    cudaFuncSetAttribute(gru_recurrent_kernel,
                         cudaFuncAttributeMaxDynamicSharedMemorySize, kSmem);

    dim3 g1(G3 / BN, (BB * TT) / BM);   // 24 x 256
    xproj_gemm_kernel<<<g1, 256>>>(x, Wih, bih);

    gru_recurrent_kernel<<<NCTA, NTHR, kSmem>>>(Whh, bhh, out);
}